// round 1
// baseline (speedup 1.0000x reference)
#include <cuda_runtime.h>
#include <cuda_bf16.h>
#include <cstdint>

// Problem constants (fixed by the dataset)
#define CN 120000
#define CM 100000
#define CD 64
#define CK 8
#define CP 16

// ---------------- scratch (device globals; no allocation allowed) ----------------
__device__ float d_Fp[CN * CP];            // normalized f@Wf.T per point
__device__ float d_Zq[CM * CP];            // normalized z@Wz.T per voxel
__device__ float d_msg[(size_t)CM * CD];   // scattered weighted features
__device__ float d_wsum[CM];               // scattered weights
__device__ int   d_cnt[CM];                // occupancy hit counts

// =====================================================================
// K1: per-point — voxel hash + binary search + count, and Fp projection
// warp handles 2 points, 16 lanes per point (lane&15 = output p)
// =====================================================================
__global__ void __launch_bounds__(256) point_kernel(
    const float* __restrict__ pts, const float* __restrict__ f_pts,
    const float* __restrict__ Wf, const int* __restrict__ keys,
    float* __restrict__ Fp, int* __restrict__ cnt, int N, int M)
{
    __shared__ float Wft[64 * 16];  // transposed [d][p]
    int tid = threadIdx.x;
    for (int i = tid; i < 16 * 64; i += 256) {
        int p = i >> 6, d = i & 63;
        Wft[d * 16 + p] = Wf[i];
    }
    __syncthreads();

    int warp = tid >> 5, lane = tid & 31;
    int n = blockIdx.x * 16 + warp * 2 + (lane >> 4);
    int p = lane & 15;

    float acc = 0.f;
    if (n < N) {
        const float4* f4 = (const float4*)(f_pts + (size_t)n * 64);
        #pragma unroll
        for (int j = 0; j < 16; j++) {
            float4 fv = f4[j];
            int d = j * 4;
            acc += Wft[d * 16 + p] * fv.x + Wft[(d + 1) * 16 + p] * fv.y
                 + Wft[(d + 2) * 16 + p] * fv.z + Wft[(d + 3) * 16 + p] * fv.w;
        }
    }
    float sq = acc * acc;
    sq += __shfl_xor_sync(~0u, sq, 1);
    sq += __shfl_xor_sync(~0u, sq, 2);
    sq += __shfl_xor_sync(~0u, sq, 4);
    sq += __shfl_xor_sync(~0u, sq, 8);
    if (n < N) {
        Fp[n * 16 + p] = acc / (sqrtf(sq) + 1e-6f);
        if (p == 0) {
            float px = pts[n * 3 + 0], py = pts[n * 3 + 1], pz = pts[n * 3 + 2];
            // IEEE division to match XLA bit-exactly (discrete decision!)
            int ix = (int)floorf(__fdiv_rn(px, 0.1f));
            int iy = (int)floorf(__fdiv_rn(py, 0.1f));
            int iz = (int)floorf(__fdiv_rn(pz, 0.1f));
            int h = ((ix + 512) << 20) ^ ((iy + 512) << 10) ^ (iz + 512);
            int lo = 0, hi = M;
            while (lo < hi) {
                int mid = (lo + hi) >> 1;
                if (keys[mid] < h) lo = mid + 1; else hi = mid;
            }
            atomicAdd(cnt + min(lo, M - 1), 1);
        }
    }
}

// =====================================================================
// K2: per-voxel — normalized Zq = normalize(z_latent @ Wz.T)
// (hoisted out of the (n,k) loop: pure function of the gathered row)
// =====================================================================
__global__ void __launch_bounds__(256) zq_kernel(
    const float* __restrict__ z_latent, const float* __restrict__ Wz,
    float* __restrict__ Zq, int M)
{
    __shared__ float Wzt[64 * 16];
    int tid = threadIdx.x;
    for (int i = tid; i < 16 * 64; i += 256) {
        int p = i >> 6, d = i & 63;
        Wzt[d * 16 + p] = Wz[i];
    }
    __syncthreads();

    int warp = tid >> 5, lane = tid & 31;
    int m = blockIdx.x * 16 + warp * 2 + (lane >> 4);
    int p = lane & 15;

    float acc = 0.f;
    if (m < M) {
        const float4* z4 = (const float4*)(z_latent + (size_t)m * 64);
        #pragma unroll
        for (int j = 0; j < 16; j++) {
            float4 zv = z4[j];
            int d = j * 4;
            acc += Wzt[d * 16 + p] * zv.x + Wzt[(d + 1) * 16 + p] * zv.y
                 + Wzt[(d + 2) * 16 + p] * zv.z + Wzt[(d + 3) * 16 + p] * zv.w;
        }
    }
    float sq = acc * acc;
    sq += __shfl_xor_sync(~0u, sq, 1);
    sq += __shfl_xor_sync(~0u, sq, 2);
    sq += __shfl_xor_sync(~0u, sq, 4);
    sq += __shfl_xor_sync(~0u, sq, 8);
    if (m < M) Zq[m * 16 + p] = acc / (sqrtf(sq) + 1e-6f);
}

// =====================================================================
// K3: per-(n,k) routing — sim, group-of-8 softmax, vectorized scatter
// =====================================================================
__global__ void __launch_bounds__(256) route_kernel(
    const float* __restrict__ pts, const float* __restrict__ f_pts,
    const float* __restrict__ centers, const int* __restrict__ cand,
    const float* __restrict__ Fp, const float* __restrict__ Zq,
    const float* __restrict__ w_delta, const float* __restrict__ b_delta,
    const float* __restrict__ log_temp,
    float* __restrict__ msg, float* __restrict__ wsum, int N)
{
    int tid = blockIdx.x * blockDim.x + threadIdx.x;
    bool valid = tid < N * 8;           // groups of 8 are all-valid or all-invalid
    int t = valid ? tid : 0;
    int n = t >> 3;
    int c = cand[t];

    const float4* fp4 = (const float4*)(Fp + n * 16);
    const float4* zq4 = (const float4*)(Zq + c * 16);
    float core = 0.f;
    #pragma unroll
    for (int j = 0; j < 4; j++) {
        float4 a = fp4[j], b = zq4[j];
        core += a.x * b.x + a.y * b.y + a.z * b.z + a.w * b.w;
    }
    float dterm = (pts[n * 3 + 0] - centers[c * 3 + 0]) * w_delta[0]
                + (pts[n * 3 + 1] - centers[c * 3 + 1]) * w_delta[1]
                + (pts[n * 3 + 2] - centers[c * 3 + 2]) * w_delta[2]
                + b_delta[0];
    float sim = expf(log_temp[0]) * (core + dterm);

    float mx = sim;
    mx = fmaxf(mx, __shfl_xor_sync(~0u, mx, 1));
    mx = fmaxf(mx, __shfl_xor_sync(~0u, mx, 2));
    mx = fmaxf(mx, __shfl_xor_sync(~0u, mx, 4));
    float e = expf((sim - mx) * (1.0f / 0.3f));
    float s = e;
    s += __shfl_xor_sync(~0u, s, 1);
    s += __shfl_xor_sync(~0u, s, 2);
    s += __shfl_xor_sync(~0u, s, 4);
    float w = e / s;

    if (valid) {
        float* mrow = msg + (size_t)c * 64;
        const float4* f4 = (const float4*)(f_pts + (size_t)n * 64);
        #pragma unroll
        for (int j = 0; j < 16; j++) {
            float4 fv = f4[j];
            asm volatile("red.global.add.v4.f32 [%0], {%1, %2, %3, %4};"
                         :: "l"(mrow + j * 4),
                            "f"(w * fv.x), "f"(w * fv.y), "f"(w * fv.z), "f"(w * fv.w)
                         : "memory");
        }
        atomicAdd(wsum + c, w);
    }
}

// =====================================================================
// K4: fused per-voxel gate + GRU + LN + decoder (+ vals output)
// all weights transposed in smem; warp processes 4 voxels so each
// weight LDS feeds 4 FMAs (FMA-bound instead of smem-crossbar-bound)
// =====================================================================
#define SMEM_FLOATS 54112
__global__ void __launch_bounds__(256, 1) voxel_mlp_kernel(
    const float* __restrict__ z_latent, const float* __restrict__ vals_st,
    const float* __restrict__ W_ih, const float* __restrict__ W_hh,
    const float* __restrict__ b_ih, const float* __restrict__ b_hh,
    const float* __restrict__ Wg1, const float* __restrict__ bg1,
    const float* __restrict__ Wg2, const float* __restrict__ bg2,
    const float* __restrict__ ln_g, const float* __restrict__ ln_b,
    const float* __restrict__ Wd1, const float* __restrict__ bd1,
    const float* __restrict__ Wd2, const float* __restrict__ bd2,
    const float* __restrict__ Wd3, const float* __restrict__ bd3,
    const float* __restrict__ msg_raw, const float* __restrict__ wsum,
    const int* __restrict__ cnt, float* __restrict__ out, int M)
{
    extern __shared__ float sm[];
    float* Wiht = sm;                    // [64][192]
    float* Whht = Wiht + 64 * 192;       // [64][192]
    float* Wg1t = Whht + 64 * 192;       // [128][32]
    float* Wd1t = Wg1t + 128 * 32;       // [64][96]
    float* Wd2t = Wd1t + 64 * 96;        // [96][96]
    float* sWg2 = Wd2t + 96 * 96;        // 32
    float* sbg1 = sWg2 + 32;             // 32
    float* sbih = sbg1 + 32;             // 192
    float* sbhh = sbih + 192;            // 192
    float* sbd1 = sbhh + 192;            // 96
    float* sbd2 = sbd1 + 96;             // 96
    float* slng = sbd2 + 96;             // 64
    float* slnb = slng + 64;             // 64
    float* sWd3 = slnb + 64;             // 96
    float* wbuf = sWd3 + 96;             // 8 warps * 1152

    int tid = threadIdx.x;

    // vals output (independent of the MLP)
    for (int m = blockIdx.x * blockDim.x + tid; m < M; m += gridDim.x * blockDim.x)
        out[M + m] = fminf(fmaxf(vals_st[m] + 0.5f * (float)cnt[m], -2.0f), 3.5f);

    // stage weights (transposed)
    for (int i = tid; i < 192 * 64; i += 256) {
        int r = i >> 6, d = i & 63;
        Wiht[d * 192 + r] = W_ih[i];
        Whht[d * 192 + r] = W_hh[i];
    }
    for (int i = tid; i < 32 * 128; i += 256) {
        int r = i >> 7, d = i & 127;
        Wg1t[d * 32 + r] = Wg1[i];
    }
    for (int i = tid; i < 96 * 64; i += 256) {
        int r = i >> 6, d = i & 63;
        Wd1t[d * 96 + r] = Wd1[i];
    }
    for (int i = tid; i < 96 * 96; i += 256) {
        int r = i / 96, d = i % 96;
        Wd2t[d * 96 + r] = Wd2[i];
    }
    if (tid < 32) { sWg2[tid] = Wg2[tid]; sbg1[tid] = bg1[tid]; }
    if (tid < 192) { sbih[tid] = b_ih[tid]; sbhh[tid] = b_hh[tid]; }
    if (tid < 96) { sbd1[tid] = bd1[tid]; sbd2[tid] = bd2[tid]; sWd3[tid] = Wd3[tid]; }
    if (tid < 64) { slng[tid] = ln_g[tid]; slnb[tid] = ln_b[tid]; }
    __syncthreads();

    float vbg2 = bg2[0], vbd3 = bd3[0];

    int warp = tid >> 5, lane = tid & 31;
    float* zsh  = wbuf + warp * 1152;    // [4][64]
    float* msh  = zsh + 256;             // [4][64]
    float* xsh  = msh + 256;             // [4][64]
    float* hdsh = xsh + 256;             // [4][96]

    int wg = blockIdx.x * 8 + warp;
    int nw = gridDim.x * 8;

    for (int base = wg * 4; base < M; base += nw * 4) {
        int nv = min(4, M - base);
        for (int v = 0; v < nv; v++) {
            int vox = base + v;
            float inv = 1.0f / (wsum[vox] + 1e-6f);
            zsh[v * 64 + lane]      = z_latent[(size_t)vox * 64 + lane];
            zsh[v * 64 + lane + 32] = z_latent[(size_t)vox * 64 + lane + 32];
            msh[v * 64 + lane]      = msg_raw[(size_t)vox * 64 + lane] * inv;
            msh[v * 64 + lane + 32] = msg_raw[(size_t)vox * 64 + lane + 32] * inv;
        }
        __syncwarp();

        // ---- gate MLP: lane = hidden unit j (HG=32) ----
        float ga0 = 0.f, ga1 = 0.f, ga2 = 0.f, ga3 = 0.f;
        #pragma unroll 4
        for (int d = 0; d < 64; d++) {
            float w1 = Wg1t[d * 32 + lane];
            float w2 = Wg1t[(64 + d) * 32 + lane];
            ga0 += w1 * zsh[d]       + w2 * msh[d];
            ga1 += w1 * zsh[64 + d]  + w2 * msh[64 + d];
            ga2 += w1 * zsh[128 + d] + w2 * msh[128 + d];
            ga3 += w1 * zsh[192 + d] + w2 * msh[192 + d];
        }
        float g[4];
        {
            float bgv = sbg1[lane], wg2v = sWg2[lane];
            float t[4] = {ga0, ga1, ga2, ga3};
            #pragma unroll
            for (int v = 0; v < 4; v++) {
                float s = wg2v * fmaxf(t[v] + bgv, 0.0f);
                #pragma unroll
                for (int o = 16; o; o >>= 1) s += __shfl_xor_sync(~0u, s, o);
                g[v] = 1.0f / (1.0f + expf(-(s + vbg2)));
            }
        }

        // ---- gi = W_ih@msg, gh = W_hh@z : lane owns rows lane+32c ----
        float A[6][4], B[6][4];
        #pragma unroll
        for (int c = 0; c < 6; c++)
            #pragma unroll
            for (int v = 0; v < 4; v++) { A[c][v] = 0.f; B[c][v] = 0.f; }
        #pragma unroll 2
        for (int d = 0; d < 64; d++) {
            float m0 = msh[d], m1 = msh[64 + d], m2 = msh[128 + d], m3 = msh[192 + d];
            float z0 = zsh[d], z1 = zsh[64 + d], z2 = zsh[128 + d], z3 = zsh[192 + d];
            #pragma unroll
            for (int c = 0; c < 6; c++) {
                float wi = Wiht[d * 192 + lane + 32 * c];
                float wh = Whht[d * 192 + lane + 32 * c];
                A[c][0] += wi * m0; A[c][1] += wi * m1; A[c][2] += wi * m2; A[c][3] += wi * m3;
                B[c][0] += wh * z0; B[c][1] += wh * z1; B[c][2] += wh * z2; B[c][3] += wh * z3;
            }
        }

        // ---- GRU + LayerNorm ----
        float bi0 = sbih[lane],       bh0 = sbhh[lane];
        float bi1 = sbih[lane + 32],  bh1 = sbhh[lane + 32];
        float bi2 = sbih[lane + 64],  bh2 = sbhh[lane + 64];
        float bi3 = sbih[lane + 96],  bh3 = sbhh[lane + 96];
        float bi4 = sbih[lane + 128], bh4 = sbhh[lane + 128];
        float bi5 = sbih[lane + 160], bh5 = sbhh[lane + 160];
        float lg0 = slng[lane], lb0 = slnb[lane];
        float lg1 = slng[lane + 32], lb1 = slnb[lane + 32];
        #pragma unroll
        for (int v = 0; v < 4; v++) {
            float r0 = 1.f / (1.f + expf(-(A[0][v] + bi0 + B[0][v] + bh0)));
            float r1 = 1.f / (1.f + expf(-(A[1][v] + bi1 + B[1][v] + bh1)));
            float u0 = 1.f / (1.f + expf(-(A[2][v] + bi2 + B[2][v] + bh2)));
            float u1 = 1.f / (1.f + expf(-(A[3][v] + bi3 + B[3][v] + bh3)));
            float n0 = tanhf(A[4][v] + bi4 + r0 * (B[4][v] + bh4));
            float n1 = tanhf(A[5][v] + bi5 + r1 * (B[5][v] + bh5));
            float z0 = zsh[v * 64 + lane], z1 = zsh[v * 64 + lane + 32];
            float h0 = (1.f - u0) * n0 + u0 * z0;
            float h1 = (1.f - u1) * n1 + u1 * z1;
            float zn0 = z0 + g[v] * (h0 - z0);
            float zn1 = z1 + g[v] * (h1 - z1);
            float s = zn0 + zn1, s2 = zn0 * zn0 + zn1 * zn1;
            #pragma unroll
            for (int o = 16; o; o >>= 1) {
                s  += __shfl_xor_sync(~0u, s, o);
                s2 += __shfl_xor_sync(~0u, s2, o);
            }
            float mu  = s * (1.0f / 64.0f);
            float var = s2 * (1.0f / 64.0f) - mu * mu;
            float is  = rsqrtf(var + 1e-5f);
            xsh[v * 64 + lane]      = (zn0 - mu) * is * lg0 + lb0;
            xsh[v * 64 + lane + 32] = (zn1 - mu) * is * lg1 + lb1;
        }
        __syncwarp();

        // ---- decoder fc1 (lane owns rows lane, lane+32, lane+64) ----
        float H[3][4];
        #pragma unroll
        for (int jr = 0; jr < 3; jr++)
            #pragma unroll
            for (int v = 0; v < 4; v++) H[jr][v] = 0.f;
        #pragma unroll 2
        for (int d = 0; d < 64; d++) {
            float x0 = xsh[d], x1 = xsh[64 + d], x2 = xsh[128 + d], x3 = xsh[192 + d];
            #pragma unroll
            for (int jr = 0; jr < 3; jr++) {
                float wd = Wd1t[d * 96 + lane + 32 * jr];
                H[jr][0] += wd * x0; H[jr][1] += wd * x1;
                H[jr][2] += wd * x2; H[jr][3] += wd * x3;
            }
        }
        #pragma unroll
        for (int jr = 0; jr < 3; jr++) {
            float b = sbd1[lane + 32 * jr];
            #pragma unroll
            for (int v = 0; v < 4; v++) {
                H[jr][v] = fmaxf(H[jr][v] + b, 0.f);
                hdsh[v * 96 + lane + 32 * jr] = H[jr][v];
            }
        }
        __syncwarp();

        // ---- decoder fc2 (residual) + fc3 + sigmoid ----
        float H2[3][4];
        #pragma unroll
        for (int jr = 0; jr < 3; jr++)
            #pragma unroll
            for (int v = 0; v < 4; v++) H2[jr][v] = 0.f;
        #pragma unroll 2
        for (int i = 0; i < 96; i++) {
            float h0 = hdsh[i], h1 = hdsh[96 + i], h2 = hdsh[192 + i], h3 = hdsh[288 + i];
            #pragma unroll
            for (int jr = 0; jr < 3; jr++) {
                float wd = Wd2t[i * 96 + lane + 32 * jr];
                H2[jr][0] += wd * h0; H2[jr][1] += wd * h1;
                H2[jr][2] += wd * h2; H2[jr][3] += wd * h3;
            }
        }
        #pragma unroll
        for (int v = 0; v < 4; v++) {
            float acc = 0.f;
            #pragma unroll
            for (int jr = 0; jr < 3; jr++) {
                int j = lane + 32 * jr;
                float hd2 = H[jr][v] + fmaxf(H2[jr][v] + sbd2[j], 0.f);
                acc += sWd3[j] * hd2;
            }
            #pragma unroll
            for (int o = 16; o; o >>= 1) acc += __shfl_xor_sync(~0u, acc, o);
            if (lane == 0 && v < nv)
                out[base + v] = 1.f / (1.f + expf(-(acc + vbd3)));
        }
        __syncwarp();
    }
}

// =====================================================================
extern "C" void kernel_launch(void* const* d_in, const int* in_sizes, int n_in,
                              void* d_out, int out_size) {
    const float* pts      = (const float*)d_in[0];
    const float* f_pts    = (const float*)d_in[1];
    const float* z_latent = (const float*)d_in[2];
    const float* vals_st  = (const float*)d_in[3];
    const float* centers  = (const float*)d_in[4];
    const float* Wf       = (const float*)d_in[5];
    const float* Wz       = (const float*)d_in[6];
    const float* w_delta  = (const float*)d_in[7];
    const float* b_delta  = (const float*)d_in[8];
    const float* log_temp = (const float*)d_in[9];
    const float* W_ih     = (const float*)d_in[10];
    const float* W_hh     = (const float*)d_in[11];
    const float* b_ih     = (const float*)d_in[12];
    const float* b_hh     = (const float*)d_in[13];
    const float* Wg1      = (const float*)d_in[14];
    const float* bg1      = (const float*)d_in[15];
    const float* Wg2      = (const float*)d_in[16];
    const float* bg2      = (const float*)d_in[17];
    const float* ln_g     = (const float*)d_in[18];
    const float* ln_b     = (const float*)d_in[19];
    const float* Wd1      = (const float*)d_in[20];
    const float* bd1      = (const float*)d_in[21];
    const float* Wd2      = (const float*)d_in[22];
    const float* bd2      = (const float*)d_in[23];
    const float* Wd3      = (const float*)d_in[24];
    const float* bd3      = (const float*)d_in[25];
    const int*   keys     = (const int*)d_in[26];
    const int*   cand     = (const int*)d_in[27];
    float* out = (float*)d_out;

    int N = in_sizes[0] / 3;
    int M = in_sizes[3];

    float *FpP, *ZqP, *msgP, *wsumP; int* cntP;
    cudaGetSymbolAddress((void**)&FpP, d_Fp);
    cudaGetSymbolAddress((void**)&ZqP, d_Zq);
    cudaGetSymbolAddress((void**)&msgP, d_msg);
    cudaGetSymbolAddress((void**)&wsumP, d_wsum);
    cudaGetSymbolAddress((void**)&cntP, d_cnt);

    cudaMemsetAsync(cntP, 0, (size_t)M * sizeof(int));
    cudaMemsetAsync(msgP, 0, (size_t)M * 64 * sizeof(float));
    cudaMemsetAsync(wsumP, 0, (size_t)M * sizeof(float));

    point_kernel<<<(N + 15) / 16, 256>>>(pts, f_pts, Wf, keys, FpP, cntP, N, M);
    zq_kernel<<<(M + 15) / 16, 256>>>(z_latent, Wz, ZqP, M);
    route_kernel<<<(N * 8 + 255) / 256, 256>>>(pts, f_pts, centers, cand, FpP, ZqP,
                                               w_delta, b_delta, log_temp,
                                               msgP, wsumP, N);

    cudaFuncSetAttribute(voxel_mlp_kernel,
                         cudaFuncAttributeMaxDynamicSharedMemorySize,
                         SMEM_FLOATS * sizeof(float));
    voxel_mlp_kernel<<<148, 256, SMEM_FLOATS * sizeof(float)>>>(
        z_latent, vals_st, W_ih, W_hh, b_ih, b_hh, Wg1, bg1, Wg2, bg2,
        ln_g, ln_b, Wd1, bd1, Wd2, bd2, Wd3, bd3, msgP, wsumP, cntP, out, M);
}

// round 2
// speedup vs baseline: 1.2722x; 1.2722x over previous
#include <cuda_runtime.h>
#include <cuda_bf16.h>
#include <cstdint>

#define CN 120000
#define CM 100000
#define CD 64
#define CK 8
#define CP 16

// ---------------- scratch (device globals) ----------------
__device__ float d_Fp[CN * CP];
__device__ float d_Zq[CM * CP];
__device__ float d_msg[(size_t)CM * CD];
__device__ float d_wsum[CM];
__device__ int   d_cnt[CM];

// ---- packed f32x2 helpers (sm_103a FFMA2 — only reachable via PTX) ----
__device__ __forceinline__ unsigned long long fma2(unsigned long long a,
                                                   unsigned long long b,
                                                   unsigned long long c) {
    unsigned long long d;
    asm("fma.rn.f32x2 %0, %1, %2, %3;" : "=l"(d) : "l"(a), "l"(b), "l"(c));
    return d;
}
__device__ __forceinline__ float2 u2f(unsigned long long v) {
    float2 f;
    asm("mov.b64 {%0, %1}, %2;" : "=f"(f.x), "=f"(f.y) : "l"(v));
    return f;
}
__device__ __forceinline__ unsigned long long f2u(float x, float y) {
    unsigned long long v;
    asm("mov.b64 %0, {%1, %2};" : "=l"(v) : "f"(x), "f"(y));
    return v;
}

// =====================================================================
// K1: per-point — voxel hash + binary search + count, and Fp projection
// =====================================================================
__global__ void __launch_bounds__(256) point_kernel(
    const float* __restrict__ pts, const float* __restrict__ f_pts,
    const float* __restrict__ Wf, const int* __restrict__ keys,
    float* __restrict__ Fp, int* __restrict__ cnt, int N, int M)
{
    __shared__ float Wft[64 * 16];
    int tid = threadIdx.x;
    for (int i = tid; i < 16 * 64; i += 256) {
        int p = i >> 6, d = i & 63;
        Wft[d * 16 + p] = Wf[i];
    }
    __syncthreads();

    int warp = tid >> 5, lane = tid & 31;
    int n = blockIdx.x * 16 + warp * 2 + (lane >> 4);
    int p = lane & 15;

    float acc = 0.f;
    if (n < N) {
        const float4* f4 = (const float4*)(f_pts + (size_t)n * 64);
        #pragma unroll
        for (int j = 0; j < 16; j++) {
            float4 fv = f4[j];
            int d = j * 4;
            acc += Wft[d * 16 + p] * fv.x + Wft[(d + 1) * 16 + p] * fv.y
                 + Wft[(d + 2) * 16 + p] * fv.z + Wft[(d + 3) * 16 + p] * fv.w;
        }
    }
    float sq = acc * acc;
    sq += __shfl_xor_sync(~0u, sq, 1);
    sq += __shfl_xor_sync(~0u, sq, 2);
    sq += __shfl_xor_sync(~0u, sq, 4);
    sq += __shfl_xor_sync(~0u, sq, 8);
    if (n < N) {
        Fp[n * 16 + p] = acc / (sqrtf(sq) + 1e-6f);
        if (p == 0) {
            float px = pts[n * 3 + 0], py = pts[n * 3 + 1], pz = pts[n * 3 + 2];
            int ix = (int)floorf(__fdiv_rn(px, 0.1f));
            int iy = (int)floorf(__fdiv_rn(py, 0.1f));
            int iz = (int)floorf(__fdiv_rn(pz, 0.1f));
            int h = ((ix + 512) << 20) ^ ((iy + 512) << 10) ^ (iz + 512);
            int lo = 0, hi = M;
            while (lo < hi) {
                int mid = (lo + hi) >> 1;
                if (keys[mid] < h) lo = mid + 1; else hi = mid;
            }
            atomicAdd(cnt + min(lo, M - 1), 1);
        }
    }
}

// =====================================================================
// K2: per-voxel — Zq = normalize(z_latent @ Wz.T)
// =====================================================================
__global__ void __launch_bounds__(256) zq_kernel(
    const float* __restrict__ z_latent, const float* __restrict__ Wz,
    float* __restrict__ Zq, int M)
{
    __shared__ float Wzt[64 * 16];
    int tid = threadIdx.x;
    for (int i = tid; i < 16 * 64; i += 256) {
        int p = i >> 6, d = i & 63;
        Wzt[d * 16 + p] = Wz[i];
    }
    __syncthreads();

    int warp = tid >> 5, lane = tid & 31;
    int m = blockIdx.x * 16 + warp * 2 + (lane >> 4);
    int p = lane & 15;

    float acc = 0.f;
    if (m < M) {
        const float4* z4 = (const float4*)(z_latent + (size_t)m * 64);
        #pragma unroll
        for (int j = 0; j < 16; j++) {
            float4 zv = z4[j];
            int d = j * 4;
            acc += Wzt[d * 16 + p] * zv.x + Wzt[(d + 1) * 16 + p] * zv.y
                 + Wzt[(d + 2) * 16 + p] * zv.z + Wzt[(d + 3) * 16 + p] * zv.w;
        }
    }
    float sq = acc * acc;
    sq += __shfl_xor_sync(~0u, sq, 1);
    sq += __shfl_xor_sync(~0u, sq, 2);
    sq += __shfl_xor_sync(~0u, sq, 4);
    sq += __shfl_xor_sync(~0u, sq, 8);
    if (m < M) Zq[m * 16 + p] = acc / (sqrtf(sq) + 1e-6f);
}

// =====================================================================
// K3: per-(n,k) routing — sim, group-of-8 softmax, vectorized scatter
// =====================================================================
__global__ void __launch_bounds__(256) route_kernel(
    const float* __restrict__ pts, const float* __restrict__ f_pts,
    const float* __restrict__ centers, const int* __restrict__ cand,
    const float* __restrict__ Fp, const float* __restrict__ Zq,
    const float* __restrict__ w_delta, const float* __restrict__ b_delta,
    const float* __restrict__ log_temp,
    float* __restrict__ msg, float* __restrict__ wsum, int N)
{
    int tid = blockIdx.x * blockDim.x + threadIdx.x;
    bool valid = tid < N * 8;
    int t = valid ? tid : 0;
    int n = t >> 3;
    int c = cand[t];

    const float4* fp4 = (const float4*)(Fp + n * 16);
    const float4* zq4 = (const float4*)(Zq + c * 16);
    float core = 0.f;
    #pragma unroll
    for (int j = 0; j < 4; j++) {
        float4 a = fp4[j], b = zq4[j];
        core += a.x * b.x + a.y * b.y + a.z * b.z + a.w * b.w;
    }
    float dterm = (pts[n * 3 + 0] - centers[c * 3 + 0]) * w_delta[0]
                + (pts[n * 3 + 1] - centers[c * 3 + 1]) * w_delta[1]
                + (pts[n * 3 + 2] - centers[c * 3 + 2]) * w_delta[2]
                + b_delta[0];
    float sim = expf(log_temp[0]) * (core + dterm);

    float mx = sim;
    mx = fmaxf(mx, __shfl_xor_sync(~0u, mx, 1));
    mx = fmaxf(mx, __shfl_xor_sync(~0u, mx, 2));
    mx = fmaxf(mx, __shfl_xor_sync(~0u, mx, 4));
    float e = expf((sim - mx) * (1.0f / 0.3f));
    float s = e;
    s += __shfl_xor_sync(~0u, s, 1);
    s += __shfl_xor_sync(~0u, s, 2);
    s += __shfl_xor_sync(~0u, s, 4);
    float w = e / s;

    if (valid) {
        float* mrow = msg + (size_t)c * 64;
        const float4* f4 = (const float4*)(f_pts + (size_t)n * 64);
        #pragma unroll
        for (int j = 0; j < 16; j++) {
            float4 fv = f4[j];
            asm volatile("red.global.add.v4.f32 [%0], {%1, %2, %3, %4};"
                         :: "l"(mrow + j * 4),
                            "f"(w * fv.x), "f"(w * fv.y), "f"(w * fv.z), "f"(w * fv.w)
                         : "memory");
        }
        atomicAdd(wsum + c, w);
    }
}

// =====================================================================
// K4: fused per-voxel gate + GRU + LN + decoder, FFMA2 edition
// 512 threads (16 warps/SM), 4 voxels/warp.
// Weights pre-PAIRED in smem so fma.rn.f32x2 needs zero pack instrs:
//   Wp[d][c][lane]  = {W_ih[c*32+lane][d], W_hh[c*32+lane][d]}
//   Wg1p[d][lane]   = {Wg1[lane][64+d],    Wg1[lane][d]}
//   data mz[v][d]   = {msg[d],             z[d]}
// =====================================================================
// smem float offsets
#define OFF_WP    0                      // 24576 floats (12288 float2)
#define OFF_WG1P  24576                  // 4096
#define OFF_WD1T  28672                  // 6144
#define OFF_WD2T  34816                  // 9216
#define OFF_SMALL 44032                  // 864
#define OFF_WBUF  44896                  // 16 * 768
#define SMEM_FLOATS (44896 + 16 * 768)   // 57184 floats = 228736 B

__global__ void __launch_bounds__(512, 1) voxel_mlp_kernel(
    const float* __restrict__ z_latent, const float* __restrict__ vals_st,
    const float* __restrict__ W_ih, const float* __restrict__ W_hh,
    const float* __restrict__ b_ih, const float* __restrict__ b_hh,
    const float* __restrict__ Wg1, const float* __restrict__ bg1,
    const float* __restrict__ Wg2, const float* __restrict__ bg2,
    const float* __restrict__ ln_g, const float* __restrict__ ln_b,
    const float* __restrict__ Wd1, const float* __restrict__ bd1,
    const float* __restrict__ Wd2, const float* __restrict__ bd2,
    const float* __restrict__ Wd3, const float* __restrict__ bd3,
    const float* __restrict__ msg_raw, const float* __restrict__ wsum,
    const int* __restrict__ cnt, float* __restrict__ out, int M)
{
    extern __shared__ float sm[];
    float2* Wp   = (float2*)(sm + OFF_WP);
    float2* Wg1p = (float2*)(sm + OFF_WG1P);
    float*  Wd1t = sm + OFF_WD1T;
    float*  Wd2t = sm + OFF_WD2T;
    float* sWg2 = sm + OFF_SMALL;        // 32
    float* sbg1 = sWg2 + 32;             // 32
    float* sbih = sbg1 + 32;             // 192
    float* sbhh = sbih + 192;            // 192
    float* sbd1 = sbhh + 192;            // 96
    float* sbd2 = sbd1 + 96;             // 96
    float* slng = sbd2 + 96;             // 64
    float* slnb = slng + 64;             // 64
    float* sWd3 = slnb + 64;             // 96

    int tid = threadIdx.x;

    // vals output
    for (int m = blockIdx.x * blockDim.x + tid; m < M; m += gridDim.x * blockDim.x)
        out[M + m] = fminf(fmaxf(vals_st[m] + 0.5f * (float)cnt[m], -2.0f), 3.5f);

    // ---- stage weights (paired layouts) ----
    for (int idx = tid; idx < 64 * 192; idx += 512) {
        int d = idx / 192, row = idx % 192;      // row = c*32+lane
        Wp[idx] = make_float2(W_ih[row * 64 + d], W_hh[row * 64 + d]);
    }
    for (int idx = tid; idx < 64 * 32; idx += 512) {
        int d = idx >> 5, j = idx & 31;
        Wg1p[idx] = make_float2(Wg1[j * 128 + 64 + d], Wg1[j * 128 + d]);
    }
    for (int i = tid; i < 96 * 64; i += 512) {
        int r = i >> 6, d = i & 63;
        Wd1t[d * 96 + r] = Wd1[i];
    }
    for (int i = tid; i < 96 * 96; i += 512) {
        int r = i / 96, d = i % 96;
        Wd2t[d * 96 + r] = Wd2[i];
    }
    if (tid < 32) { sWg2[tid] = Wg2[tid]; sbg1[tid] = bg1[tid]; }
    if (tid < 192) { sbih[tid] = b_ih[tid]; sbhh[tid] = b_hh[tid]; }
    if (tid < 96) { sbd1[tid] = bd1[tid]; sbd2[tid] = bd2[tid]; sWd3[tid] = Wd3[tid]; }
    if (tid < 64) { slng[tid] = ln_g[tid]; slnb[tid] = ln_b[tid]; }
    __syncthreads();

    float vbg2 = bg2[0], vbd3 = bd3[0];

    int warp = tid >> 5, lane = tid & 31;
    float* wbuf = sm + OFF_WBUF + warp * 768;
    float2* mz = (float2*)wbuf;                        // [4][64] pairs {m,z}
    float*  xT = wbuf + 512;                           // [64][4]
    float*  hT = wbuf;                                 // [96][4] (aliases mz; mz dead by then)
    const unsigned long long* mzB  = (const unsigned long long*)wbuf;
    const unsigned long long* WpB  = (const unsigned long long*)Wp;
    const unsigned long long* Wg1B = (const unsigned long long*)Wg1p;

    // hoisted per-lane constants
    float bi0 = sbih[lane],       bh0 = sbhh[lane];
    float bi1 = sbih[lane + 32],  bh1 = sbhh[lane + 32];
    float bi2 = sbih[lane + 64],  bh2 = sbhh[lane + 64];
    float bi3 = sbih[lane + 96],  bh3 = sbhh[lane + 96];
    float bi4 = sbih[lane + 128], bh4 = sbhh[lane + 128];
    float bi5 = sbih[lane + 160], bh5 = sbhh[lane + 160];
    float lg0 = slng[lane], lb0 = slnb[lane];
    float lg1 = slng[lane + 32], lb1 = slnb[lane + 32];
    float bgv = sbg1[lane], wg2v = sWg2[lane];

    int wg = blockIdx.x * 16 + warp;
    int nw = gridDim.x * 16;

    for (int base = wg * 4; base < M; base += nw * 4) {
        int nv = min(4, M - base);
        for (int v = 0; v < nv; v++) {
            int vox = base + v;
            float inv = 1.0f / (wsum[vox] + 1e-6f);
            float z0 = z_latent[(size_t)vox * 64 + lane];
            float z1 = z_latent[(size_t)vox * 64 + lane + 32];
            float m0 = msg_raw[(size_t)vox * 64 + lane] * inv;
            float m1 = msg_raw[(size_t)vox * 64 + lane + 32] * inv;
            mz[v * 64 + lane]      = make_float2(m0, z0);
            mz[v * 64 + lane + 32] = make_float2(m1, z1);
        }
        __syncwarp();

        // ---- merged gate + GRU projections (FFMA2) ----
        unsigned long long AB[6][4], G[4];
        #pragma unroll
        for (int c = 0; c < 6; c++)
            #pragma unroll
            for (int v = 0; v < 4; v++) AB[c][v] = 0ull;
        #pragma unroll
        for (int v = 0; v < 4; v++) G[v] = 0ull;

        #pragma unroll 2
        for (int d = 0; d < 64; d++) {
            unsigned long long q0 = mzB[d];
            unsigned long long q1 = mzB[64 + d];
            unsigned long long q2 = mzB[128 + d];
            unsigned long long q3 = mzB[192 + d];
            unsigned long long wg1 = Wg1B[d * 32 + lane];
            G[0] = fma2(wg1, q0, G[0]);
            G[1] = fma2(wg1, q1, G[1]);
            G[2] = fma2(wg1, q2, G[2]);
            G[3] = fma2(wg1, q3, G[3]);
            #pragma unroll
            for (int c = 0; c < 6; c++) {
                unsigned long long wp = WpB[(d * 6 + c) * 32 + lane];
                AB[c][0] = fma2(wp, q0, AB[c][0]);
                AB[c][1] = fma2(wp, q1, AB[c][1]);
                AB[c][2] = fma2(wp, q2, AB[c][2]);
                AB[c][3] = fma2(wp, q3, AB[c][3]);
            }
        }

        // ---- gate reduce ----
        float g[4];
        #pragma unroll
        for (int v = 0; v < 4; v++) {
            float2 gf = u2f(G[v]);
            float s = wg2v * fmaxf(gf.x + gf.y + bgv, 0.0f);
            #pragma unroll
            for (int o = 16; o; o >>= 1) s += __shfl_xor_sync(~0u, s, o);
            g[v] = 1.0f / (1.0f + expf(-(s + vbg2)));
        }

        // ---- GRU + LayerNorm; write xT[d][v] ----
        #pragma unroll
        for (int v = 0; v < 4; v++) {
            float2 a0 = u2f(AB[0][v]), a1 = u2f(AB[1][v]);
            float2 a2 = u2f(AB[2][v]), a3 = u2f(AB[3][v]);
            float2 a4 = u2f(AB[4][v]), a5 = u2f(AB[5][v]);
            float r0 = 1.f / (1.f + expf(-(a0.x + bi0 + a0.y + bh0)));
            float r1 = 1.f / (1.f + expf(-(a1.x + bi1 + a1.y + bh1)));
            float u0 = 1.f / (1.f + expf(-(a2.x + bi2 + a2.y + bh2)));
            float u1 = 1.f / (1.f + expf(-(a3.x + bi3 + a3.y + bh3)));
            float n0 = tanhf(a4.x + bi4 + r0 * (a4.y + bh4));
            float n1 = tanhf(a5.x + bi5 + r1 * (a5.y + bh5));
            float z0 = mz[v * 64 + lane].y;
            float z1 = mz[v * 64 + lane + 32].y;
            float h0 = (1.f - u0) * n0 + u0 * z0;
            float h1 = (1.f - u1) * n1 + u1 * z1;
            float zn0 = z0 + g[v] * (h0 - z0);
            float zn1 = z1 + g[v] * (h1 - z1);
            float s = zn0 + zn1, s2 = zn0 * zn0 + zn1 * zn1;
            #pragma unroll
            for (int o = 16; o; o >>= 1) {
                s  += __shfl_xor_sync(~0u, s, o);
                s2 += __shfl_xor_sync(~0u, s2, o);
            }
            float mu  = s * (1.0f / 64.0f);
            float var = s2 * (1.0f / 64.0f) - mu * mu;
            float is  = rsqrtf(var + 1e-5f);
            xT[lane * 4 + v]        = (zn0 - mu) * is * lg0 + lb0;
            xT[(lane + 32) * 4 + v] = (zn1 - mu) * is * lg1 + lb1;
        }
        __syncwarp();

        // ---- decoder fc1 (FFMA2 over voxel pairs) ----
        unsigned long long Hp[3][2];
        #pragma unroll
        for (int jr = 0; jr < 3; jr++) { Hp[jr][0] = 0ull; Hp[jr][1] = 0ull; }
        const unsigned long long* xB = (const unsigned long long*)xT;
        #pragma unroll 2
        for (int d = 0; d < 64; d++) {
            unsigned long long x01 = xB[d * 2];
            unsigned long long x23 = xB[d * 2 + 1];
            #pragma unroll
            for (int jr = 0; jr < 3; jr++) {
                float wd = Wd1t[d * 96 + lane + 32 * jr];
                unsigned long long wpp = f2u(wd, wd);
                Hp[jr][0] = fma2(wpp, x01, Hp[jr][0]);
                Hp[jr][1] = fma2(wpp, x23, Hp[jr][1]);
            }
        }
        float H[3][4];
        #pragma unroll
        for (int jr = 0; jr < 3; jr++) {
            float b = sbd1[lane + 32 * jr];
            float2 f01 = u2f(Hp[jr][0]), f23 = u2f(Hp[jr][1]);
            H[jr][0] = fmaxf(f01.x + b, 0.f);
            H[jr][1] = fmaxf(f01.y + b, 0.f);
            H[jr][2] = fmaxf(f23.x + b, 0.f);
            H[jr][3] = fmaxf(f23.y + b, 0.f);
        }
        __syncwarp();    // mz fully dead -> hT can be written
        #pragma unroll
        for (int jr = 0; jr < 3; jr++) {
            int j = lane + 32 * jr;
            hT[j * 4 + 0] = H[jr][0];
            hT[j * 4 + 1] = H[jr][1];
            hT[j * 4 + 2] = H[jr][2];
            hT[j * 4 + 3] = H[jr][3];
        }
        __syncwarp();

        // ---- decoder fc2 (residual) + fc3 + sigmoid ----
        unsigned long long Hp2[3][2];
        #pragma unroll
        for (int jr = 0; jr < 3; jr++) { Hp2[jr][0] = 0ull; Hp2[jr][1] = 0ull; }
        const unsigned long long* hB = (const unsigned long long*)hT;
        #pragma unroll 2
        for (int i = 0; i < 96; i++) {
            unsigned long long h01 = hB[i * 2];
            unsigned long long h23 = hB[i * 2 + 1];
            #pragma unroll
            for (int jr = 0; jr < 3; jr++) {
                float wd = Wd2t[i * 96 + lane + 32 * jr];
                unsigned long long wpp = f2u(wd, wd);
                Hp2[jr][0] = fma2(wpp, h01, Hp2[jr][0]);
                Hp2[jr][1] = fma2(wpp, h23, Hp2[jr][1]);
            }
        }
        float acc[4] = {0.f, 0.f, 0.f, 0.f};
        #pragma unroll
        for (int jr = 0; jr < 3; jr++) {
            int j = lane + 32 * jr;
            float b2 = sbd2[j], w3 = sWd3[j];
            float2 f01 = u2f(Hp2[jr][0]), f23 = u2f(Hp2[jr][1]);
            acc[0] += w3 * (H[jr][0] + fmaxf(f01.x + b2, 0.f));
            acc[1] += w3 * (H[jr][1] + fmaxf(f01.y + b2, 0.f));
            acc[2] += w3 * (H[jr][2] + fmaxf(f23.x + b2, 0.f));
            acc[3] += w3 * (H[jr][3] + fmaxf(f23.y + b2, 0.f));
        }
        #pragma unroll
        for (int v = 0; v < 4; v++) {
            float a = acc[v];
            #pragma unroll
            for (int o = 16; o; o >>= 1) a += __shfl_xor_sync(~0u, a, o);
            if (lane == 0 && v < nv)
                out[base + v] = 1.f / (1.f + expf(-(a + vbd3)));
        }
        __syncwarp();
    }
}

// =====================================================================
extern "C" void kernel_launch(void* const* d_in, const int* in_sizes, int n_in,
                              void* d_out, int out_size) {
    const float* pts      = (const float*)d_in[0];
    const float* f_pts    = (const float*)d_in[1];
    const float* z_latent = (const float*)d_in[2];
    const float* vals_st  = (const float*)d_in[3];
    const float* centers  = (const float*)d_in[4];
    const float* Wf       = (const float*)d_in[5];
    const float* Wz       = (const float*)d_in[6];
    const float* w_delta  = (const float*)d_in[7];
    const float* b_delta  = (const float*)d_in[8];
    const float* log_temp = (const float*)d_in[9];
    const float* W_ih     = (const float*)d_in[10];
    const float* W_hh     = (const float*)d_in[11];
    const float* b_ih     = (const float*)d_in[12];
    const float* b_hh     = (const float*)d_in[13];
    const float* Wg1      = (const float*)d_in[14];
    const float* bg1      = (const float*)d_in[15];
    const float* Wg2      = (const float*)d_in[16];
    const float* bg2      = (const float*)d_in[17];
    const float* ln_g     = (const float*)d_in[18];
    const float* ln_b     = (const float*)d_in[19];
    const float* Wd1      = (const float*)d_in[20];
    const float* bd1      = (const float*)d_in[21];
    const float* Wd2      = (const float*)d_in[22];
    const float* bd2      = (const float*)d_in[23];
    const float* Wd3      = (const float*)d_in[24];
    const float* bd3      = (const float*)d_in[25];
    const int*   keys     = (const int*)d_in[26];
    const int*   cand     = (const int*)d_in[27];
    float* out = (float*)d_out;

    int N = in_sizes[0] / 3;
    int M = in_sizes[3];

    float *FpP, *ZqP, *msgP, *wsumP; int* cntP;
    cudaGetSymbolAddress((void**)&FpP, d_Fp);
    cudaGetSymbolAddress((void**)&ZqP, d_Zq);
    cudaGetSymbolAddress((void**)&msgP, d_msg);
    cudaGetSymbolAddress((void**)&wsumP, d_wsum);
    cudaGetSymbolAddress((void**)&cntP, d_cnt);

    cudaMemsetAsync(cntP, 0, (size_t)M * sizeof(int));
    cudaMemsetAsync(msgP, 0, (size_t)M * 64 * sizeof(float));
    cudaMemsetAsync(wsumP, 0, (size_t)M * sizeof(float));

    point_kernel<<<(N + 15) / 16, 256>>>(pts, f_pts, Wf, keys, FpP, cntP, N, M);
    zq_kernel<<<(M + 15) / 16, 256>>>(z_latent, Wz, ZqP, M);
    route_kernel<<<(N * 8 + 255) / 256, 256>>>(pts, f_pts, centers, cand, FpP, ZqP,
                                               w_delta, b_delta, log_temp,
                                               msgP, wsumP, N);

    cudaFuncSetAttribute(voxel_mlp_kernel,
                         cudaFuncAttributeMaxDynamicSharedMemorySize,
                         SMEM_FLOATS * sizeof(float));
    voxel_mlp_kernel<<<148, 512, SMEM_FLOATS * sizeof(float)>>>(
        z_latent, vals_st, W_ih, W_hh, b_ih, b_hh, Wg1, bg1, Wg2, bg2,
        ln_g, ln_b, Wd1, bd1, Wd2, bd2, Wd3, bd3, msgP, wsumP, cntP, out, M);
}